// round 13
// baseline (speedup 1.0000x reference)
#include <cuda_runtime.h>
#include <cuda_fp16.h>
#include <cstdint>

// CapsuleConv = GEMM (rows=(b,w,a)=130944, K=(k,n,x)=384, cols=(m,d)=128) + fused LayerNorm.
// Single-pass fp16 mma.sync, warp-specialized: 6 compute warps (96x128 tile) + 1 producer
// warp issuing B via cp.async + mbarrier (.noinc arrivals — pre-counted in init).
// Zero mid-loop CTA barriers. 2 CTAs/SM.

#define BB    16
#define NIN   32
#define LLEN  2048
#define MMO   32
#define WOUTN 2046

#define THREADS 224
#define NCOMP   192         // 6 compute warps
#define WTILE   24          // w per CTA (M = 96 output rows)
#define ASTRIDE 272         // smem row stride bytes
#define A_ROWS  104         // (WTILE + 2) * 4
#define A_MAT   (A_ROWS * ASTRIDE)        // 28288
#define B_MAT   (128 * ASTRIDE)           // 34816
#define OFF_B   A_MAT
#define OFF_MBAR (OFF_B + 2 * B_MAT)      // 97920
#define SMEM_BYTES (OFF_MBAR + 64)        // 97984 -> 2 CTAs/SM
#define WSTRIDE 68          // warp-local epilogue scratch stride (floats)
#define OUT_SCALE (1.0f / 32.0f)
#define A_PAIRS (A_ROWS * 16)             // 1664

// ---- persistent scratch: rearranged fp16 weight ----
__device__ __half g_B[3 * 128 * 128];     // B[k][c=m*4+d][n*4+x] = w (unscaled)

// ======================= helpers =======================
__device__ __forceinline__ uint32_t smem_u32(const void* p) {
    uint32_t a;
    asm("{ .reg .u64 t; cvta.to.shared.u64 t, %1; cvt.u32.u64 %0, t; }" : "=r"(a) : "l"(p));
    return a;
}
__device__ __forceinline__ void cp16(uint32_t dst, const void* src) {
    asm volatile("cp.async.cg.shared.global [%0], [%1], 16;" :: "r"(dst), "l"(src));
}
__device__ __forceinline__ void mbar_init(uint32_t mbar, uint32_t cnt) {
    asm volatile("mbarrier.init.shared.b64 [%0], %1;" :: "r"(mbar), "r"(cnt) : "memory");
}
__device__ __forceinline__ void mbar_arrive(uint32_t mbar) {
    asm volatile("mbarrier.arrive.shared.b64 _, [%0];" :: "r"(mbar) : "memory");
}
// .noinc: arrival counts against the PRE-SET expected count (init),
// instead of the default self-balancing increment+arrive (which nets zero).
__device__ __forceinline__ void cp_arrive(uint32_t mbar) {
    asm volatile("cp.async.mbarrier.arrive.noinc.shared.b64 [%0];" :: "r"(mbar) : "memory");
}
__device__ __forceinline__ void mbar_wait(uint32_t mbar, uint32_t parity) {
    asm volatile(
        "{\n\t.reg .pred P;\n\t"
        "W%=:\n\t"
        "mbarrier.try_wait.parity.shared.b64 P, [%0], %1;\n\t"
        "@!P bra W%=;\n\t}"
        :: "r"(mbar), "r"(parity) : "memory");
}
__device__ __forceinline__ void ldsm4(uint32_t* r, uint32_t addr) {
    asm volatile("ldmatrix.sync.aligned.m8n8.x4.shared.b16 {%0,%1,%2,%3}, [%4];"
                 : "=r"(r[0]), "=r"(r[1]), "=r"(r[2]), "=r"(r[3]) : "r"(addr));
}
__device__ __forceinline__ void mma16816(float* d, const uint32_t* a,
                                         uint32_t b0, uint32_t b1) {
    asm volatile(
        "mma.sync.aligned.m16n8k16.row.col.f32.f16.f16.f32 "
        "{%0,%1,%2,%3}, {%4,%5,%6,%7}, {%8,%9}, {%0,%1,%2,%3};"
        : "+f"(d[0]), "+f"(d[1]), "+f"(d[2]), "+f"(d[3])
        : "r"(a[0]), "r"(a[1]), "r"(a[2]), "r"(a[3]), "r"(b0), "r"(b1));
}
__device__ __forceinline__ uint32_t pkh(__half a, __half b) {
    __half2 t(a, b);
    return *reinterpret_cast<uint32_t*>(&t);
}

// ======================= tiny prepass: rearrange + convert weight =======================
__global__ __launch_bounds__(256)
void prep_b(const float* __restrict__ w) {
    const int idx = blockIdx.x * 256 + threadIdx.x;   // < 49152
    const int col = idx & 127;       // n*4+x
    const int row = idx >> 7;
    const int c = row & 127;         // m*4+d
    const int k = row >> 7;
    const int n = col >> 2, xx = col & 3;
    const int m = c >> 2, d = c & 3;
    g_B[idx] = __float2half_rn(w[(((k * NIN + n) * 4 + xx) * 4 + d) * MMO + m]);
}

// ======================= main kernel =======================
__global__ __launch_bounds__(THREADS, 2)
void caps_mma_kernel(const float* __restrict__ x,
                     const float* __restrict__ gamma,
                     const float* __restrict__ beta,
                     float* __restrict__ out) {
    extern __shared__ char dsm[];
    const uint32_t smem = smem_u32(dsm);

    const int tid = threadIdx.x;
    const int wid = tid >> 5, lid = tid & 31;
    const int b  = blockIdx.y;
    const int w0 = blockIdx.x * WTILE;

    const uint32_t mb_ready = smem + OFF_MBAR;       // A(192 threads) + B0 cp (32 noinc) = 224
    const uint32_t mb_b1    = smem + OFF_MBAR + 8;   // 32 (noinc)
    const uint32_t mb_b2    = smem + OFF_MBAR + 16;  // 32 (noinc)
    const uint32_t mb_free  = smem + OFF_MBAR + 24;  // 192 (compute after k0)

    if (tid == 0) {
        mbar_init(mb_ready, NCOMP + 32);
        mbar_init(mb_b1, 32);
        mbar_init(mb_b2, 32);
        mbar_init(mb_free, NCOMP);
    }
    __syncthreads();

    const float* xb = x + (size_t)b * NIN * LLEN * 16;

    float d[2][8][4];
    const int wm = wid >> 1;          // rows wm*32 .. +32   (0..2)
    const int wn = wid & 1;           // cols wn*64 .. +64

    if (wid == 6) {
        // =================== producer warp: B slices via cp.async ===================
        // B0 -> buf0
#pragma unroll
        for (int i = 0; i < 64; ++i) {
            const int u = lid + 32 * i;               // < 2048
            const int row = u >> 4, seg = u & 15;
            cp16(smem + OFF_B + (uint32_t)(row * ASTRIDE + seg * 16),
                 g_B + (size_t)row * 128 + seg * 8);
        }
        cp_arrive(mb_ready);
        // B1 -> buf1
#pragma unroll
        for (int i = 0; i < 64; ++i) {
            const int u = lid + 32 * i;
            const int row = u >> 4, seg = u & 15;
            cp16(smem + OFF_B + B_MAT + (uint32_t)(row * ASTRIDE + seg * 16),
                 g_B + (size_t)(128 + row) * 128 + seg * 8);
        }
        cp_arrive(mb_b1);
        // wait buf0 free (compute past k0), then B2 -> buf0
        mbar_wait(mb_free, 0);
#pragma unroll
        for (int i = 0; i < 64; ++i) {
            const int u = lid + 32 * i;
            const int row = u >> 4, seg = u & 15;
            cp16(smem + OFF_B + (uint32_t)(row * ASTRIDE + seg * 16),
                 g_B + (size_t)(256 + row) * 128 + seg * 8);
        }
        cp_arrive(mb_b2);
    } else {
        // =================== compute warps ===================
        // ---- build A tile: paired LDG.128 fp32 -> f2h -> STS.128 ----
        // pair u: s = u/104 (col seg), r = u%104 (row = ll*4+a); sources nl = 2s, 2s+1.
#pragma unroll
        for (int j = 0; j < 9; ++j) {
            const int u = tid + NCOMP * j;
            if (u < A_PAIRS) {
                const int s = u / A_ROWS;
                const int r = u - s * A_ROWS;
                const int a  = r & 3;
                const int ll = r >> 2;
                int l = w0 + ll; if (l > LLEN - 1) l = LLEN - 1;  // overhang rows only
                const float* base = xb + ((size_t)(2 * s) * LLEN + l) * 16 + a * 4;
                const float4 v0 = *reinterpret_cast<const float4*>(base);
                const float4 v1 = *reinterpret_cast<const float4*>(base + (size_t)LLEN * 16);
                *reinterpret_cast<uint4*>(dsm + (uint32_t)(r * ASTRIDE + s * 16)) =
                    make_uint4(pkh(__float2half_rn(v0.x), __float2half_rn(v0.y)),
                               pkh(__float2half_rn(v0.z), __float2half_rn(v0.w)),
                               pkh(__float2half_rn(v1.x), __float2half_rn(v1.y)),
                               pkh(__float2half_rn(v1.z), __float2half_rn(v1.w)));
            }
        }
        mbar_arrive(mb_ready);       // release: A STS visible to acquirers

#pragma unroll
        for (int i = 0; i < 2; i++)
#pragma unroll
            for (int j = 0; j < 8; j++)
#pragma unroll
                for (int q = 0; q < 4; q++) d[i][j][q] = 0.0f;

        const uint32_t lane_off = (uint32_t)((lid & 15) * ASTRIDE + (lid >> 4) * 16);

        mbar_wait(mb_ready, 0);      // A + B0 ready

        for (int k = 0; k < 3; ++k) {
            if (k == 1)      mbar_wait(mb_b1, 0);
            else if (k == 2) mbar_wait(mb_b2, 0);

            uint32_t aA0 = smem + (uint32_t)((wm * 32 + 4 * k) * ASTRIDE) + lane_off;
            uint32_t aA1 = aA0 + 16 * ASTRIDE;
            uint32_t aB0 = smem + OFF_B + (uint32_t)((k & 1) ? B_MAT : 0)
                         + (uint32_t)(wn * 64 * ASTRIDE) + lane_off;
            uint32_t aB1 = aB0 + 16 * ASTRIDE;
            uint32_t aB2 = aB0 + 32 * ASTRIDE;
            uint32_t aB3 = aB0 + 48 * ASTRIDE;

#pragma unroll
            for (int ks = 0; ks < 8; ++ks) {
                uint32_t Ar[2][4], Br[4][4];
                ldsm4(Ar[0], aA0); ldsm4(Ar[1], aA1);
                ldsm4(Br[0], aB0); ldsm4(Br[1], aB1);
                ldsm4(Br[2], aB2); ldsm4(Br[3], aB3);
                aA0 += 32; aA1 += 32; aB0 += 32; aB1 += 32; aB2 += 32; aB3 += 32;
#pragma unroll
                for (int mf = 0; mf < 2; ++mf)
#pragma unroll
                    for (int bg = 0; bg < 4; ++bg) {
                        mma16816(d[mf][bg * 2],     Ar[mf], Br[bg][0], Br[bg][2]);
                        mma16816(d[mf][bg * 2 + 1], Ar[mf], Br[bg][1], Br[bg][3]);
                    }
            }
            if (k == 0) mbar_arrive(mb_free);   // buf0 reads done -> producer may fill B2
        }
    }

    // ---- single CTA barrier, then warp-local epilogue (compute warps only) ----
    __syncthreads();
    if (wid < 6) {
        float* Sw = reinterpret_cast<float*>(dsm) + wid * (32 * WSTRIDE);   // 8.7KB/warp
        const int g = lid >> 2, t4 = lid & 3;
#pragma unroll
        for (int mf = 0; mf < 2; ++mf)
#pragma unroll
            for (int ng = 0; ng < 8; ++ng) {
                const int r = mf * 16 + g;
                const int c = ng * 8 + t4 * 2;
                Sw[r * WSTRIDE + c]           = d[mf][ng][0];
                Sw[r * WSTRIDE + c + 1]       = d[mf][ng][1];
                Sw[(r + 8) * WSTRIDE + c]     = d[mf][ng][2];
                Sw[(r + 8) * WSTRIDE + c + 1] = d[mf][ng][3];
            }
        __syncwarp();

        float gam[16], bet[16];
#pragma unroll
        for (int i = 0; i < 16; i++) { gam[i] = __ldg(gamma + i); bet[i] = __ldg(beta + i); }

        // 128 LN groups per warp (8 wl x 16 m), 4 per lane
#pragma unroll
        for (int q = 0; q < 4; ++q) {
            const int G  = lid + 32 * q;
            const int wl = G >> 4;
            const int ml = G & 15;
            const int w  = w0 + wm * 8 + wl;
            const int m  = wn * 16 + ml;
            if (w >= WOUTN) continue;

            float vals[16];
#pragma unroll
            for (int a = 0; a < 4; a++) {
                const float4 v = *reinterpret_cast<const float4*>(
                    Sw + (wl * 4 + a) * WSTRIDE + ml * 4);
                vals[a * 4 + 0] = v.x * OUT_SCALE; vals[a * 4 + 1] = v.y * OUT_SCALE;
                vals[a * 4 + 2] = v.z * OUT_SCALE; vals[a * 4 + 3] = v.w * OUT_SCALE;
            }
            float mu = 0.0f;
#pragma unroll
            for (int i = 0; i < 16; i++) mu += vals[i];
            mu *= 0.0625f;
            float var = 0.0f;
#pragma unroll
            for (int i = 0; i < 16; i++) {
                const float dv = vals[i] - mu;
                var = fmaf(dv, dv, var);
            }
            var *= 0.0625f;
            const float inv = rsqrtf(var + 1e-5f);

            const size_t base = (((size_t)b * MMO + m) * WOUTN + w) * 16;
#pragma unroll
            for (int p = 0; p < 4; p++) {
                float4 o;
                o.x = fmaf((vals[p * 4 + 0] - mu) * inv, gam[p * 4 + 0], bet[p * 4 + 0]);
                o.y = fmaf((vals[p * 4 + 1] - mu) * inv, gam[p * 4 + 1], bet[p * 4 + 1]);
                o.z = fmaf((vals[p * 4 + 2] - mu) * inv, gam[p * 4 + 2], bet[p * 4 + 2]);
                o.w = fmaf((vals[p * 4 + 3] - mu) * inv, gam[p * 4 + 3], bet[p * 4 + 3]);
                *reinterpret_cast<float4*>(out + base + p * 4) = o;
            }
        }
    }
}

extern "C" void kernel_launch(void* const* d_in, const int* in_sizes, int n_in,
                              void* d_out, int out_size) {
    const float* x     = (const float*)d_in[0];
    const float* w     = (const float*)d_in[1];
    const float* gamma = (const float*)d_in[2];
    const float* beta  = (const float*)d_in[3];
    float* out = (float*)d_out;

    prep_b<<<192, 256>>>(w);

    cudaFuncSetAttribute(caps_mma_kernel,
                         cudaFuncAttributeMaxDynamicSharedMemorySize, SMEM_BYTES);
    dim3 grid(86, BB);   // 86 w-tiles (24 w each, ceil(2046/24)) x 16 batches
    caps_mma_kernel<<<grid, THREADS, SMEM_BYTES>>>(x, gamma, beta, out);
}

// round 14
// speedup vs baseline: 1.2455x; 1.2455x over previous
#include <cuda_runtime.h>
#include <cuda_fp16.h>
#include <cstdint>

// CapsuleConv = GEMM (rows=(b,w,a)=130944, K=(k,n,x)=384, cols=(m,d)=128) + fused LayerNorm.
// Single-pass fp16 mma.sync (R11 structure), plus:
//  - one fewer mid-loop CTA barrier (combined B1-visibility + buf0-free barrier)
//  - eps-folded LayerNorm (no output-scale multiplies: eps' = 1024*eps)

#define BB    16
#define NIN   32
#define LLEN  2048
#define MMO   32
#define WOUTN 2046

#define THREADS 256
#define WTILE   32          // w per CTA (M = 128 output rows)
#define ASTRIDE 272         // smem row stride bytes (128 fp16 = 256B + 16 pad)
#define A_ROWS  136         // (WTILE + 2) * 4
#define A_MAT   (A_ROWS * ASTRIDE)        // 36992
#define B_MAT   (128 * ASTRIDE)           // 34816
#define OFF_B   A_MAT
#define SMEM_BYTES (A_MAT + 2 * B_MAT)    // 106624 -> 2 CTAs/SM
#define WSTRIDE 68          // warp-local epilogue scratch stride (floats)
#define EPS_FOLDED 1.024e-2f              // 1e-5 * 32^2 (LN on 32x-scaled values)

// ---- persistent scratch: rearranged fp16 weight ----
__device__ __half g_B[3 * 128 * 128];     // B[k][c=m*4+d][n*4+x] = w (unscaled)

// ======================= helpers =======================
__device__ __forceinline__ uint32_t smem_u32(const void* p) {
    uint32_t a;
    asm("{ .reg .u64 t; cvta.to.shared.u64 t, %1; cvt.u32.u64 %0, t; }" : "=r"(a) : "l"(p));
    return a;
}
__device__ __forceinline__ void cp16(uint32_t dst, const void* src) {
    asm volatile("cp.async.cg.shared.global [%0], [%1], 16;" :: "r"(dst), "l"(src));
}
__device__ __forceinline__ void cp_commit() {
    asm volatile("cp.async.commit_group;" ::: "memory");
}
__device__ __forceinline__ void ldsm4(uint32_t* r, uint32_t addr) {
    asm volatile("ldmatrix.sync.aligned.m8n8.x4.shared.b16 {%0,%1,%2,%3}, [%4];"
                 : "=r"(r[0]), "=r"(r[1]), "=r"(r[2]), "=r"(r[3]) : "r"(addr));
}
__device__ __forceinline__ void mma16816(float* d, const uint32_t* a,
                                         uint32_t b0, uint32_t b1) {
    asm volatile(
        "mma.sync.aligned.m16n8k16.row.col.f32.f16.f16.f32 "
        "{%0,%1,%2,%3}, {%4,%5,%6,%7}, {%8,%9}, {%0,%1,%2,%3};"
        : "+f"(d[0]), "+f"(d[1]), "+f"(d[2]), "+f"(d[3])
        : "r"(a[0]), "r"(a[1]), "r"(a[2]), "r"(a[3]), "r"(b0), "r"(b1));
}
__device__ __forceinline__ uint32_t pkh(__half a, __half b) {
    __half2 t(a, b);
    return *reinterpret_cast<uint32_t*>(&t);
}

// ======================= tiny prepass: rearrange + convert weight =======================
__global__ __launch_bounds__(256)
void prep_b(const float* __restrict__ w) {
    const int idx = blockIdx.x * 256 + threadIdx.x;   // < 49152
    const int col = idx & 127;       // n*4+x
    const int row = idx >> 7;
    const int c = row & 127;         // m*4+d
    const int k = row >> 7;
    const int n = col >> 2, xx = col & 3;
    const int m = c >> 2, d = c & 3;
    g_B[idx] = __float2half_rn(w[(((k * NIN + n) * 4 + xx) * 4 + d) * MMO + m]);
}

// ======================= main kernel =======================
__global__ __launch_bounds__(THREADS, 2)
void caps_mma_kernel(const float* __restrict__ x,
                     const float* __restrict__ gamma,
                     const float* __restrict__ beta,
                     float* __restrict__ out) {
    extern __shared__ char dsm[];
    const uint32_t smem = smem_u32(dsm);

    const int tid = threadIdx.x;
    const int wid = tid >> 5, lid = tid & 31;
    const int b  = blockIdx.y;
    const int w0 = blockIdx.x * WTILE;

    const int wm = wid & 3;           // rows wm*32 .. +32
    const int wn = wid >> 2;          // cols wn*64 .. +64
    const uint32_t lane_off = (uint32_t)((lid & 15) * ASTRIDE + (lid >> 4) * 16);

    const float* xb = x + (size_t)b * NIN * LLEN * 16;

    // ---- issue B[0] into buf0 (2048 cp16, 8/thread) ----
#pragma unroll
    for (int j = 0; j < 8; ++j) {
        const int u = tid + THREADS * j;
        const int row = u >> 4, seg = u & 15;
        cp16(smem + OFF_B + (uint32_t)(row * ASTRIDE + seg * 16),
             g_B + (size_t)row * 128 + seg * 8);
    }
    cp_commit();   // group 0: B0

    // ---- issue B[1] into buf1 ----
#pragma unroll
    for (int j = 0; j < 8; ++j) {
        const int u = tid + THREADS * j;
        const int row = u >> 4, seg = u & 15;
        cp16(smem + OFF_B + B_MAT + (uint32_t)(row * ASTRIDE + seg * 16),
             g_B + (size_t)(128 + row) * 128 + seg * 8);
    }
    cp_commit();   // group 1: B1

    // ---- build A tile inline: paired LDG.128 fp32 -> f2h -> one STS.128 ----
    // pair P -> (a, ll, s): sources nl = 2s, 2s+1; dst 16B at row*ASTRIDE + s*16.
    // Part 1: ll in [0,32): no clamp (w0+31 <= 2047). 2048 pairs, 8/thread.
#pragma unroll
    for (int j = 0; j < 8; ++j) {
        const int P  = tid + THREADS * j;
        const int a  = P & 3;
        const int ll = (P >> 2) & 31;
        const int s  = P >> 7;            // 0..15
        const float* base = xb + ((size_t)(2 * s) * LLEN + (w0 + ll)) * 16 + a * 4;
        const float4 v0 = *reinterpret_cast<const float4*>(base);
        const float4 v1 = *reinterpret_cast<const float4*>(base + (size_t)LLEN * 16);
        *reinterpret_cast<uint4*>(dsm + (uint32_t)((ll * 4 + a) * ASTRIDE + s * 16)) =
            make_uint4(pkh(__float2half_rn(v0.x), __float2half_rn(v0.y)),
                       pkh(__float2half_rn(v0.z), __float2half_rn(v0.w)),
                       pkh(__float2half_rn(v1.x), __float2half_rn(v1.y)),
                       pkh(__float2half_rn(v1.z), __float2half_rn(v1.w)));
    }
    // Part 2: ll in {32,33} (overhang; clamp; garbage only for w>=WOUT, never stored)
    if (tid < 128) {
        const int a  = tid & 3;
        const int ll = 32 + ((tid >> 2) & 1);
        const int s  = tid >> 3;          // 0..15
        int l = w0 + ll; if (l > LLEN - 1) l = LLEN - 1;
        const float* base = xb + ((size_t)(2 * s) * LLEN + l) * 16 + a * 4;
        const float4 v0 = *reinterpret_cast<const float4*>(base);
        const float4 v1 = *reinterpret_cast<const float4*>(base + (size_t)LLEN * 16);
        *reinterpret_cast<uint4*>(dsm + (uint32_t)((ll * 4 + a) * ASTRIDE + s * 16)) =
            make_uint4(pkh(__float2half_rn(v0.x), __float2half_rn(v0.y)),
                       pkh(__float2half_rn(v0.z), __float2half_rn(v0.w)),
                       pkh(__float2half_rn(v1.x), __float2half_rn(v1.y)),
                       pkh(__float2half_rn(v1.z), __float2half_rn(v1.w)));
    }

    float d[2][8][4];
#pragma unroll
    for (int i = 0; i < 2; i++)
#pragma unroll
        for (int j = 0; j < 8; j++)
#pragma unroll
            for (int q = 0; q < 4; q++) d[i][j][q] = 0.0f;

    for (int k = 0; k < 3; ++k) {
        if (k == 0) {
            asm volatile("cp.async.wait_group 1;" ::: "memory");   // own B0 done
            __syncthreads();               // A STS + everyone's B0 visible
        } else if (k == 1) {
            asm volatile("cp.async.wait_group 0;" ::: "memory");   // own B1 done
            __syncthreads();               // all B1 visible AND all buf0 reads done
            // buf0 free: issue B2 into it (overlaps k1 compute)
#pragma unroll
            for (int j = 0; j < 8; ++j) {
                const int u = tid + THREADS * j;
                const int row = u >> 4, seg = u & 15;
                cp16(smem + OFF_B + (uint32_t)(row * ASTRIDE + seg * 16),
                     g_B + (size_t)(256 + row) * 128 + seg * 8);
            }
            cp_commit();   // group 2: B2
        } else {
            asm volatile("cp.async.wait_group 0;" ::: "memory");   // own B2 done
            __syncthreads();               // all B2 visible
        }

        // incremented LDSM address registers (+32B per k16 step)
        uint32_t aA0 = smem + (uint32_t)((wm * 32 + 4 * k) * ASTRIDE) + lane_off;
        uint32_t aA1 = aA0 + 16 * ASTRIDE;
        uint32_t aB0 = smem + OFF_B + (uint32_t)((k & 1) ? B_MAT : 0)
                     + (uint32_t)(wn * 64 * ASTRIDE) + lane_off;
        uint32_t aB1 = aB0 + 16 * ASTRIDE;
        uint32_t aB2 = aB0 + 32 * ASTRIDE;
        uint32_t aB3 = aB0 + 48 * ASTRIDE;

#pragma unroll
        for (int ks = 0; ks < 8; ++ks) {
            uint32_t Ar[2][4], Br[4][4];
            ldsm4(Ar[0], aA0); ldsm4(Ar[1], aA1);
            ldsm4(Br[0], aB0); ldsm4(Br[1], aB1);
            ldsm4(Br[2], aB2); ldsm4(Br[3], aB3);
            aA0 += 32; aA1 += 32; aB0 += 32; aB1 += 32; aB2 += 32; aB3 += 32;
#pragma unroll
            for (int mf = 0; mf < 2; ++mf)
#pragma unroll
                for (int bg = 0; bg < 4; ++bg) {
                    mma16816(d[mf][bg * 2],     Ar[mf], Br[bg][0], Br[bg][2]);
                    mma16816(d[mf][bg * 2 + 1], Ar[mf], Br[bg][1], Br[bg][3]);
                }
        }
    }

    // ---- epilogue: ONE barrier, then warp-local staging + LayerNorm ----
    // LN computed on 32x-scaled accumulators with eps' = 1024*eps (exact identity):
    //   gamma*(v-mu)/sqrt(var+eps) == gamma*(raw-mu_raw)*rsqrt(var_raw + 1024*eps)
    __syncthreads();   // all LDSM reads of A/B done; smem reusable as scratch
    float* Sw = reinterpret_cast<float*>(dsm) + wid * (32 * WSTRIDE);   // 8.7KB/warp
    const int g = lid >> 2, t4 = lid & 3;
#pragma unroll
    for (int mf = 0; mf < 2; ++mf)
#pragma unroll
        for (int ng = 0; ng < 8; ++ng) {
            const int r = mf * 16 + g;               // warp-local row 0..31
            const int c = ng * 8 + t4 * 2;           // warp-local col 0..63
            Sw[r * WSTRIDE + c]           = d[mf][ng][0];
            Sw[r * WSTRIDE + c + 1]       = d[mf][ng][1];
            Sw[(r + 8) * WSTRIDE + c]     = d[mf][ng][2];
            Sw[(r + 8) * WSTRIDE + c + 1] = d[mf][ng][3];
        }
    __syncwarp();

    float gam[16], bet[16];
#pragma unroll
    for (int i = 0; i < 16; i++) { gam[i] = __ldg(gamma + i); bet[i] = __ldg(beta + i); }

    // 128 LN groups per warp (8 wl x 16 m), 4 per lane
#pragma unroll
    for (int q = 0; q < 4; ++q) {
        const int G  = lid + 32 * q;                 // 0..127
        const int wl = G >> 4;                       // warp-local 0..7
        const int ml = G & 15;                       // warp-local 0..15
        const int w  = w0 + wm * 8 + wl;
        const int m  = wn * 16 + ml;
        if (w >= WOUTN) continue;

        float vals[16];
#pragma unroll
        for (int a = 0; a < 4; a++) {
            const float4 v = *reinterpret_cast<const float4*>(
                Sw + (wl * 4 + a) * WSTRIDE + ml * 4);
            vals[a * 4 + 0] = v.x; vals[a * 4 + 1] = v.y;
            vals[a * 4 + 2] = v.z; vals[a * 4 + 3] = v.w;
        }
        float mu = 0.0f;
#pragma unroll
        for (int i = 0; i < 16; i++) mu += vals[i];
        mu *= 0.0625f;
        float var = 0.0f;
#pragma unroll
        for (int i = 0; i < 16; i++) {
            const float dv = vals[i] - mu;
            var = fmaf(dv, dv, var);
        }
        var *= 0.0625f;
        const float inv = rsqrtf(var + EPS_FOLDED);

        const size_t base = (((size_t)b * MMO + m) * WOUTN + w) * 16;
#pragma unroll
        for (int p = 0; p < 4; p++) {
            float4 o;
            o.x = fmaf((vals[p * 4 + 0] - mu) * inv, gam[p * 4 + 0], bet[p * 4 + 0]);
            o.y = fmaf((vals[p * 4 + 1] - mu) * inv, gam[p * 4 + 1], bet[p * 4 + 1]);
            o.z = fmaf((vals[p * 4 + 2] - mu) * inv, gam[p * 4 + 2], bet[p * 4 + 2]);
            o.w = fmaf((vals[p * 4 + 3] - mu) * inv, gam[p * 4 + 3], bet[p * 4 + 3]);
            *reinterpret_cast<float4*>(out + base + p * 4) = o;
        }
    }
}

extern "C" void kernel_launch(void* const* d_in, const int* in_sizes, int n_in,
                              void* d_out, int out_size) {
    const float* x     = (const float*)d_in[0];
    const float* w     = (const float*)d_in[1];
    const float* gamma = (const float*)d_in[2];
    const float* beta  = (const float*)d_in[3];
    float* out = (float*)d_out;

    prep_b<<<192, 256>>>(w);

    cudaFuncSetAttribute(caps_mma_kernel,
                         cudaFuncAttributeMaxDynamicSharedMemorySize, SMEM_BYTES);
    dim3 grid(64, BB);   // 64 w-tiles x 16 batches
    caps_mma_kernel<<<grid, THREADS, SMEM_BYTES>>>(x, gamma, beta, out);
}

// round 15
// speedup vs baseline: 1.2486x; 1.0025x over previous
#include <cuda_runtime.h>
#include <cuda_fp16.h>
#include <cstdint>

// CapsuleConv = GEMM (rows=(b,w,a)=130944, K=(k,n,x)=384, cols=(m,d)=128) + fused LayerNorm.
// Single-pass fp16 mma.sync (R14 structure) + register double-buffered B fragments:
// each ks-block's 4 B-LDSMs are issued one block ahead, hidden under the MMAs of the
// current block. A fragments stay single-buffered (reg budget).

#define BB    16
#define NIN   32
#define LLEN  2048
#define MMO   32
#define WOUTN 2046

#define THREADS 256
#define WTILE   32          // w per CTA (M = 128 output rows)
#define ASTRIDE 272         // smem row stride bytes (128 fp16 = 256B + 16 pad)
#define A_ROWS  136         // (WTILE + 2) * 4
#define A_MAT   (A_ROWS * ASTRIDE)        // 36992
#define B_MAT   (128 * ASTRIDE)           // 34816
#define OFF_B   A_MAT
#define SMEM_BYTES (A_MAT + 2 * B_MAT)    // 106624 -> 2 CTAs/SM
#define WSTRIDE 68          // warp-local epilogue scratch stride (floats)
#define EPS_FOLDED 1.024e-2f              // 1e-5 * 32^2 (LN on 32x-scaled values)

// ---- persistent scratch: rearranged fp16 weight ----
__device__ __half g_B[3 * 128 * 128];     // B[k][c=m*4+d][n*4+x] = w (unscaled)

// ======================= helpers =======================
__device__ __forceinline__ uint32_t smem_u32(const void* p) {
    uint32_t a;
    asm("{ .reg .u64 t; cvta.to.shared.u64 t, %1; cvt.u32.u64 %0, t; }" : "=r"(a) : "l"(p));
    return a;
}
__device__ __forceinline__ void cp16(uint32_t dst, const void* src) {
    asm volatile("cp.async.cg.shared.global [%0], [%1], 16;" :: "r"(dst), "l"(src));
}
__device__ __forceinline__ void cp_commit() {
    asm volatile("cp.async.commit_group;" ::: "memory");
}
__device__ __forceinline__ void ldsm4(uint32_t* r, uint32_t addr) {
    asm volatile("ldmatrix.sync.aligned.m8n8.x4.shared.b16 {%0,%1,%2,%3}, [%4];"
                 : "=r"(r[0]), "=r"(r[1]), "=r"(r[2]), "=r"(r[3]) : "r"(addr));
}
__device__ __forceinline__ void mma16816(float* d, const uint32_t* a,
                                         uint32_t b0, uint32_t b1) {
    asm volatile(
        "mma.sync.aligned.m16n8k16.row.col.f32.f16.f16.f32 "
        "{%0,%1,%2,%3}, {%4,%5,%6,%7}, {%8,%9}, {%0,%1,%2,%3};"
        : "+f"(d[0]), "+f"(d[1]), "+f"(d[2]), "+f"(d[3])
        : "r"(a[0]), "r"(a[1]), "r"(a[2]), "r"(a[3]), "r"(b0), "r"(b1));
}
__device__ __forceinline__ uint32_t pkh(__half a, __half b) {
    __half2 t(a, b);
    return *reinterpret_cast<uint32_t*>(&t);
}

// ======================= tiny prepass: rearrange + convert weight =======================
__global__ __launch_bounds__(256)
void prep_b(const float* __restrict__ w) {
    const int idx = blockIdx.x * 256 + threadIdx.x;   // < 49152
    const int col = idx & 127;       // n*4+x
    const int row = idx >> 7;
    const int c = row & 127;         // m*4+d
    const int k = row >> 7;
    const int n = col >> 2, xx = col & 3;
    const int m = c >> 2, d = c & 3;
    g_B[idx] = __float2half_rn(w[(((k * NIN + n) * 4 + xx) * 4 + d) * MMO + m]);
}

// ======================= main kernel =======================
__global__ __launch_bounds__(THREADS, 2)
void caps_mma_kernel(const float* __restrict__ x,
                     const float* __restrict__ gamma,
                     const float* __restrict__ beta,
                     float* __restrict__ out) {
    extern __shared__ char dsm[];
    const uint32_t smem = smem_u32(dsm);

    const int tid = threadIdx.x;
    const int wid = tid >> 5, lid = tid & 31;
    const int b  = blockIdx.y;
    const int w0 = blockIdx.x * WTILE;

    const int wm = wid & 3;           // rows wm*32 .. +32
    const int wn = wid >> 2;          // cols wn*64 .. +64
    const uint32_t lane_off = (uint32_t)((lid & 15) * ASTRIDE + (lid >> 4) * 16);

    const float* xb = x + (size_t)b * NIN * LLEN * 16;

    // ---- issue B[0] into buf0 (2048 cp16, 8/thread) ----
#pragma unroll
    for (int j = 0; j < 8; ++j) {
        const int u = tid + THREADS * j;
        const int row = u >> 4, seg = u & 15;
        cp16(smem + OFF_B + (uint32_t)(row * ASTRIDE + seg * 16),
             g_B + (size_t)row * 128 + seg * 8);
    }
    cp_commit();   // group 0: B0

    // ---- issue B[1] into buf1 ----
#pragma unroll
    for (int j = 0; j < 8; ++j) {
        const int u = tid + THREADS * j;
        const int row = u >> 4, seg = u & 15;
        cp16(smem + OFF_B + B_MAT + (uint32_t)(row * ASTRIDE + seg * 16),
             g_B + (size_t)(128 + row) * 128 + seg * 8);
    }
    cp_commit();   // group 1: B1

    // ---- build A tile inline: paired LDG.128 fp32 -> f2h -> one STS.128 ----
    // Part 1: ll in [0,32): no clamp (w0+31 <= 2047). 2048 pairs, 8/thread.
#pragma unroll
    for (int j = 0; j < 8; ++j) {
        const int P  = tid + THREADS * j;
        const int a  = P & 3;
        const int ll = (P >> 2) & 31;
        const int s  = P >> 7;            // 0..15
        const float* base = xb + ((size_t)(2 * s) * LLEN + (w0 + ll)) * 16 + a * 4;
        const float4 v0 = *reinterpret_cast<const float4*>(base);
        const float4 v1 = *reinterpret_cast<const float4*>(base + (size_t)LLEN * 16);
        *reinterpret_cast<uint4*>(dsm + (uint32_t)((ll * 4 + a) * ASTRIDE + s * 16)) =
            make_uint4(pkh(__float2half_rn(v0.x), __float2half_rn(v0.y)),
                       pkh(__float2half_rn(v0.z), __float2half_rn(v0.w)),
                       pkh(__float2half_rn(v1.x), __float2half_rn(v1.y)),
                       pkh(__float2half_rn(v1.z), __float2half_rn(v1.w)));
    }
    // Part 2: ll in {32,33} (overhang; clamp; garbage only for w>=WOUT, never stored)
    if (tid < 128) {
        const int a  = tid & 3;
        const int ll = 32 + ((tid >> 2) & 1);
        const int s  = tid >> 3;          // 0..15
        int l = w0 + ll; if (l > LLEN - 1) l = LLEN - 1;
        const float* base = xb + ((size_t)(2 * s) * LLEN + l) * 16 + a * 4;
        const float4 v0 = *reinterpret_cast<const float4*>(base);
        const float4 v1 = *reinterpret_cast<const float4*>(base + (size_t)LLEN * 16);
        *reinterpret_cast<uint4*>(dsm + (uint32_t)((ll * 4 + a) * ASTRIDE + s * 16)) =
            make_uint4(pkh(__float2half_rn(v0.x), __float2half_rn(v0.y)),
                       pkh(__float2half_rn(v0.z), __float2half_rn(v0.w)),
                       pkh(__float2half_rn(v1.x), __float2half_rn(v1.y)),
                       pkh(__float2half_rn(v1.z), __float2half_rn(v1.w)));
    }

    float d[2][8][4];
#pragma unroll
    for (int i = 0; i < 2; i++)
#pragma unroll
        for (int j = 0; j < 8; j++)
#pragma unroll
            for (int q = 0; q < 4; q++) d[i][j][q] = 0.0f;

    for (int k = 0; k < 3; ++k) {
        if (k == 0) {
            asm volatile("cp.async.wait_group 1;" ::: "memory");   // own B0 done
            __syncthreads();               // A STS + everyone's B0 visible
        } else if (k == 1) {
            asm volatile("cp.async.wait_group 0;" ::: "memory");   // own B1 done
            __syncthreads();               // all B1 visible AND all buf0 reads done
            // buf0 free: issue B2 into it (overlaps k1 compute)
#pragma unroll
            for (int j = 0; j < 8; ++j) {
                const int u = tid + THREADS * j;
                const int row = u >> 4, seg = u & 15;
                cp16(smem + OFF_B + (uint32_t)(row * ASTRIDE + seg * 16),
                     g_B + (size_t)(256 + row) * 128 + seg * 8);
            }
            cp_commit();   // group 2: B2
        } else {
            asm volatile("cp.async.wait_group 0;" ::: "memory");   // own B2 done
            __syncthreads();               // all B2 visible
        }

        uint32_t aA0 = smem + (uint32_t)((wm * 32 + 4 * k) * ASTRIDE) + lane_off;
        uint32_t aA1 = aA0 + 16 * ASTRIDE;
        uint32_t aB0 = smem + OFF_B + (uint32_t)((k & 1) ? B_MAT : 0)
                     + (uint32_t)(wn * 64 * ASTRIDE) + lane_off;
        uint32_t aB1 = aB0 + 16 * ASTRIDE;
        uint32_t aB2 = aB0 + 32 * ASTRIDE;
        uint32_t aB3 = aB0 + 48 * ASTRIDE;

        // ---- register double-buffered B: prologue loads block 0 ----
        uint32_t Br[2][4][4];
        ldsm4(Br[0][0], aB0); ldsm4(Br[0][1], aB1);
        ldsm4(Br[0][2], aB2); ldsm4(Br[0][3], aB3);
        aB0 += 32; aB1 += 32; aB2 += 32; aB3 += 32;

#pragma unroll
        for (int ks = 0; ks < 8; ++ks) {
            const int cur = ks & 1, nxt = cur ^ 1;
            uint32_t Ar[2][4];
            ldsm4(Ar[0], aA0); ldsm4(Ar[1], aA1);
            aA0 += 32; aA1 += 32;
            if (ks < 7) {   // prefetch next block's B under this block's MMAs
                ldsm4(Br[nxt][0], aB0); ldsm4(Br[nxt][1], aB1);
                ldsm4(Br[nxt][2], aB2); ldsm4(Br[nxt][3], aB3);
                aB0 += 32; aB1 += 32; aB2 += 32; aB3 += 32;
            }
#pragma unroll
            for (int mf = 0; mf < 2; ++mf)
#pragma unroll
                for (int bg = 0; bg < 4; ++bg) {
                    mma16816(d[mf][bg * 2],     Ar[mf], Br[cur][bg][0], Br[cur][bg][2]);
                    mma16816(d[mf][bg * 2 + 1], Ar[mf], Br[cur][bg][1], Br[cur][bg][3]);
                }
        }
    }

    // ---- epilogue: ONE barrier, then warp-local staging + LayerNorm ----
    __syncthreads();   // all LDSM reads of A/B done; smem reusable as scratch
    float* Sw = reinterpret_cast<float*>(dsm) + wid * (32 * WSTRIDE);   // 8.7KB/warp
    const int g = lid >> 2, t4 = lid & 3;
#pragma unroll
    for (int mf = 0; mf < 2; ++mf)
#pragma unroll
        for (int ng = 0; ng < 8; ++ng) {
            const int r = mf * 16 + g;               // warp-local row 0..31
            const int c = ng * 8 + t4 * 2;           // warp-local col 0..63
            Sw[r * WSTRIDE + c]           = d[mf][ng][0];
            Sw[r * WSTRIDE + c + 1]       = d[mf][ng][1];
            Sw[(r + 8) * WSTRIDE + c]     = d[mf][ng][2];
            Sw[(r + 8) * WSTRIDE + c + 1] = d[mf][ng][3];
        }
    __syncwarp();

    float gam[16], bet[16];
#pragma unroll
    for (int i = 0; i < 16; i++) { gam[i] = __ldg(gamma + i); bet[i] = __ldg(beta + i); }

    // 128 LN groups per warp (8 wl x 16 m), 4 per lane
#pragma unroll
    for (int q = 0; q < 4; ++q) {
        const int G  = lid + 32 * q;                 // 0..127
        const int wl = G >> 4;                       // warp-local 0..7
        const int ml = G & 15;                       // warp-local 0..15
        const int w  = w0 + wm * 8 + wl;
        const int m  = wn * 16 + ml;
        if (w >= WOUTN) continue;

        float vals[16];
#pragma unroll
        for (int a = 0; a < 4; a++) {
            const float4 v = *reinterpret_cast<const float4*>(
                Sw + (wl * 4 + a) * WSTRIDE + ml * 4);
            vals[a * 4 + 0] = v.x; vals[a * 4 + 1] = v.y;
            vals[a * 4 + 2] = v.z; vals[a * 4 + 3] = v.w;
        }
        float mu = 0.0f;
#pragma unroll
        for (int i = 0; i < 16; i++) mu += vals[i];
        mu *= 0.0625f;
        float var = 0.0f;
#pragma unroll
        for (int i = 0; i < 16; i++) {
            const float dv = vals[i] - mu;
            var = fmaf(dv, dv, var);
        }
        var *= 0.0625f;
        const float inv = rsqrtf(var + EPS_FOLDED);

        const size_t base = (((size_t)b * MMO + m) * WOUTN + w) * 16;
#pragma unroll
        for (int p = 0; p < 4; p++) {
            float4 o;
            o.x = fmaf((vals[p * 4 + 0] - mu) * inv, gam[p * 4 + 0], bet[p * 4 + 0]);
            o.y = fmaf((vals[p * 4 + 1] - mu) * inv, gam[p * 4 + 1], bet[p * 4 + 1]);
            o.z = fmaf((vals[p * 4 + 2] - mu) * inv, gam[p * 4 + 2], bet[p * 4 + 2]);
            o.w = fmaf((vals[p * 4 + 3] - mu) * inv, gam[p * 4 + 3], bet[p * 4 + 3]);
            *reinterpret_cast<float4*>(out + base + p * 4) = o;
        }
    }
}

extern "C" void kernel_launch(void* const* d_in, const int* in_sizes, int n_in,
                              void* d_out, int out_size) {
    const float* x     = (const float*)d_in[0];
    const float* w     = (const float*)d_in[1];
    const float* gamma = (const float*)d_in[2];
    const float* beta  = (const float*)d_in[3];
    float* out = (float*)d_out;

    prep_b<<<192, 256>>>(w);

    cudaFuncSetAttribute(caps_mma_kernel,
                         cudaFuncAttributeMaxDynamicSharedMemorySize, SMEM_BYTES);
    dim3 grid(64, BB);   // 64 w-tiles x 16 batches
    caps_mma_kernel<<<grid, THREADS, SMEM_BYTES>>>(x, gamma, beta, out);
}

// round 16
// speedup vs baseline: 1.4803x; 1.1855x over previous
#include <cuda_runtime.h>
#include <cuda_fp16.h>
#include <cstdint>

// CapsuleConv = GEMM (rows=(b,w,a)=130944, K=(k,n,x)=384, cols=(m,d)=128) + fused LayerNorm.
// Single-pass fp16 mma.sync (R15 structure) + shfl-only epilogue:
// LN groups (4 a-rows x 4 d-cols) == 8-lane butterfly (masks 1,4,8) on the mma fragment
// layout -> no barrier, no smem staging, direct coalesced STG.64.

#define BB    16
#define NIN   32
#define LLEN  2048
#define MMO   32
#define WOUTN 2046

#define THREADS 256
#define WTILE   32          // w per CTA (M = 128 output rows)
#define ASTRIDE 272         // smem row stride bytes (128 fp16 = 256B + 16 pad)
#define A_ROWS  136         // (WTILE + 2) * 4
#define A_MAT   (A_ROWS * ASTRIDE)        // 36992
#define B_MAT   (128 * ASTRIDE)           // 34816
#define OFF_B   A_MAT
#define SMEM_BYTES (A_MAT + 2 * B_MAT)    // 106624 -> 2 CTAs/SM
#define EPS_FOLDED 1.024e-2f              // 1e-5 * 32^2 (LN on 32x-scaled values)

// ---- persistent scratch: rearranged fp16 weight ----
__device__ __half g_B[3 * 128 * 128];     // B[k][c=m*4+d][n*4+x] = w (unscaled)

// ======================= helpers =======================
__device__ __forceinline__ uint32_t smem_u32(const void* p) {
    uint32_t a;
    asm("{ .reg .u64 t; cvta.to.shared.u64 t, %1; cvt.u32.u64 %0, t; }" : "=r"(a) : "l"(p));
    return a;
}
__device__ __forceinline__ void cp16(uint32_t dst, const void* src) {
    asm volatile("cp.async.cg.shared.global [%0], [%1], 16;" :: "r"(dst), "l"(src));
}
__device__ __forceinline__ void cp_commit() {
    asm volatile("cp.async.commit_group;" ::: "memory");
}
__device__ __forceinline__ void ldsm4(uint32_t* r, uint32_t addr) {
    asm volatile("ldmatrix.sync.aligned.m8n8.x4.shared.b16 {%0,%1,%2,%3}, [%4];"
                 : "=r"(r[0]), "=r"(r[1]), "=r"(r[2]), "=r"(r[3]) : "r"(addr));
}
__device__ __forceinline__ void mma16816(float* d, const uint32_t* a,
                                         uint32_t b0, uint32_t b1) {
    asm volatile(
        "mma.sync.aligned.m16n8k16.row.col.f32.f16.f16.f32 "
        "{%0,%1,%2,%3}, {%4,%5,%6,%7}, {%8,%9}, {%0,%1,%2,%3};"
        : "+f"(d[0]), "+f"(d[1]), "+f"(d[2]), "+f"(d[3])
        : "r"(a[0]), "r"(a[1]), "r"(a[2]), "r"(a[3]), "r"(b0), "r"(b1));
}
__device__ __forceinline__ uint32_t pkh(__half a, __half b) {
    __half2 t(a, b);
    return *reinterpret_cast<uint32_t*>(&t);
}

// ======================= tiny prepass: rearrange + convert weight =======================
__global__ __launch_bounds__(256)
void prep_b(const float* __restrict__ w) {
    const int idx = blockIdx.x * 256 + threadIdx.x;   // < 49152
    const int col = idx & 127;       // n*4+x
    const int row = idx >> 7;
    const int c = row & 127;         // m*4+d
    const int k = row >> 7;
    const int n = col >> 2, xx = col & 3;
    const int m = c >> 2, d = c & 3;
    g_B[idx] = __float2half_rn(w[(((k * NIN + n) * 4 + xx) * 4 + d) * MMO + m]);
}

// ======================= main kernel =======================
__global__ __launch_bounds__(THREADS, 2)
void caps_mma_kernel(const float* __restrict__ x,
                     const float* __restrict__ gamma,
                     const float* __restrict__ beta,
                     float* __restrict__ out) {
    extern __shared__ char dsm[];
    const uint32_t smem = smem_u32(dsm);

    const int tid = threadIdx.x;
    const int wid = tid >> 5, lid = tid & 31;
    const int b  = blockIdx.y;
    const int w0 = blockIdx.x * WTILE;

    const int wm = wid & 3;           // rows wm*32 .. +32
    const int wn = wid >> 2;          // cols wn*64 .. +64
    const uint32_t lane_off = (uint32_t)((lid & 15) * ASTRIDE + (lid >> 4) * 16);

    const float* xb = x + (size_t)b * NIN * LLEN * 16;

    // ---- issue B[0] into buf0 (2048 cp16, 8/thread) ----
#pragma unroll
    for (int j = 0; j < 8; ++j) {
        const int u = tid + THREADS * j;
        const int row = u >> 4, seg = u & 15;
        cp16(smem + OFF_B + (uint32_t)(row * ASTRIDE + seg * 16),
             g_B + (size_t)row * 128 + seg * 8);
    }
    cp_commit();   // group 0: B0

    // ---- issue B[1] into buf1 ----
#pragma unroll
    for (int j = 0; j < 8; ++j) {
        const int u = tid + THREADS * j;
        const int row = u >> 4, seg = u & 15;
        cp16(smem + OFF_B + B_MAT + (uint32_t)(row * ASTRIDE + seg * 16),
             g_B + (size_t)(128 + row) * 128 + seg * 8);
    }
    cp_commit();   // group 1: B1

    // ---- build A tile inline: paired LDG.128 fp32 -> f2h -> one STS.128 ----
    // Part 1: ll in [0,32): no clamp (w0+31 <= 2047). 2048 pairs, 8/thread.
#pragma unroll
    for (int j = 0; j < 8; ++j) {
        const int P  = tid + THREADS * j;
        const int a  = P & 3;
        const int ll = (P >> 2) & 31;
        const int s  = P >> 7;            // 0..15
        const float* base = xb + ((size_t)(2 * s) * LLEN + (w0 + ll)) * 16 + a * 4;
        const float4 v0 = *reinterpret_cast<const float4*>(base);
        const float4 v1 = *reinterpret_cast<const float4*>(base + (size_t)LLEN * 16);
        *reinterpret_cast<uint4*>(dsm + (uint32_t)((ll * 4 + a) * ASTRIDE + s * 16)) =
            make_uint4(pkh(__float2half_rn(v0.x), __float2half_rn(v0.y)),
                       pkh(__float2half_rn(v0.z), __float2half_rn(v0.w)),
                       pkh(__float2half_rn(v1.x), __float2half_rn(v1.y)),
                       pkh(__float2half_rn(v1.z), __float2half_rn(v1.w)));
    }
    // Part 2: ll in {32,33} (overhang; clamp; garbage only for w>=WOUT, never stored)
    if (tid < 128) {
        const int a  = tid & 3;
        const int ll = 32 + ((tid >> 2) & 1);
        const int s  = tid >> 3;          // 0..15
        int l = w0 + ll; if (l > LLEN - 1) l = LLEN - 1;
        const float* base = xb + ((size_t)(2 * s) * LLEN + l) * 16 + a * 4;
        const float4 v0 = *reinterpret_cast<const float4*>(base);
        const float4 v1 = *reinterpret_cast<const float4*>(base + (size_t)LLEN * 16);
        *reinterpret_cast<uint4*>(dsm + (uint32_t)((ll * 4 + a) * ASTRIDE + s * 16)) =
            make_uint4(pkh(__float2half_rn(v0.x), __float2half_rn(v0.y)),
                       pkh(__float2half_rn(v0.z), __float2half_rn(v0.w)),
                       pkh(__float2half_rn(v1.x), __float2half_rn(v1.y)),
                       pkh(__float2half_rn(v1.z), __float2half_rn(v1.w)));
    }

    float d[2][8][4];
#pragma unroll
    for (int i = 0; i < 2; i++)
#pragma unroll
        for (int j = 0; j < 8; j++)
#pragma unroll
            for (int q = 0; q < 4; q++) d[i][j][q] = 0.0f;

    for (int k = 0; k < 3; ++k) {
        if (k == 0) {
            asm volatile("cp.async.wait_group 1;" ::: "memory");   // own B0 done
            __syncthreads();               // A STS + everyone's B0 visible
        } else if (k == 1) {
            asm volatile("cp.async.wait_group 0;" ::: "memory");   // own B1 done
            __syncthreads();               // all B1 visible AND all buf0 reads done
            // buf0 free: issue B2 into it (overlaps k1 compute)
#pragma unroll
            for (int j = 0; j < 8; ++j) {
                const int u = tid + THREADS * j;
                const int row = u >> 4, seg = u & 15;
                cp16(smem + OFF_B + (uint32_t)(row * ASTRIDE + seg * 16),
                     g_B + (size_t)(256 + row) * 128 + seg * 8);
            }
            cp_commit();   // group 2: B2
        } else {
            asm volatile("cp.async.wait_group 0;" ::: "memory");   // own B2 done
            __syncthreads();               // all B2 visible
        }

        uint32_t aA0 = smem + (uint32_t)((wm * 32 + 4 * k) * ASTRIDE) + lane_off;
        uint32_t aA1 = aA0 + 16 * ASTRIDE;
        uint32_t aB0 = smem + OFF_B + (uint32_t)((k & 1) ? B_MAT : 0)
                     + (uint32_t)(wn * 64 * ASTRIDE) + lane_off;
        uint32_t aB1 = aB0 + 16 * ASTRIDE;
        uint32_t aB2 = aB0 + 32 * ASTRIDE;
        uint32_t aB3 = aB0 + 48 * ASTRIDE;

        // register double-buffered B fragments
        uint32_t Br[2][4][4];
        ldsm4(Br[0][0], aB0); ldsm4(Br[0][1], aB1);
        ldsm4(Br[0][2], aB2); ldsm4(Br[0][3], aB3);
        aB0 += 32; aB1 += 32; aB2 += 32; aB3 += 32;

#pragma unroll
        for (int ks = 0; ks < 8; ++ks) {
            const int cur = ks & 1, nxt = cur ^ 1;
            uint32_t Ar[2][4];
            ldsm4(Ar[0], aA0); ldsm4(Ar[1], aA1);
            aA0 += 32; aA1 += 32;
            if (ks < 7) {
                ldsm4(Br[nxt][0], aB0); ldsm4(Br[nxt][1], aB1);
                ldsm4(Br[nxt][2], aB2); ldsm4(Br[nxt][3], aB3);
                aB0 += 32; aB1 += 32; aB2 += 32; aB3 += 32;
            }
#pragma unroll
            for (int mf = 0; mf < 2; ++mf)
#pragma unroll
                for (int bg = 0; bg < 4; ++bg) {
                    mma16816(d[mf][bg * 2],     Ar[mf], Br[cur][bg][0], Br[cur][bg][2]);
                    mma16816(d[mf][bg * 2 + 1], Ar[mf], Br[cur][bg][1], Br[cur][bg][3]);
                }
        }
    }

    // ======= shfl-only epilogue: no barrier, no smem =======
    // Fragment layout (m16n8k16 C): lane(g=lid>>2, t4=lid&3) holds
    //   d0,d1: row r_lo = wm*32+mf*16+g,   cols c0 = wn*64+ng*8+t4*2, c0+1
    //   d2,d3: row r_lo+8, same cols.
    // LN group = rows 4wl..4wl+3 x cols 4m..4m+3 -> lanes lid^{1,4,8}
    //   (bit1 = m selector fixed, bit4 = wl-quad fixed). Each lane contributes 2 elems
    //   per group (lo and hi rows are in DIFFERENT groups; reduce both through the
    //   same butterfly since masks keep g-quad invariant).
    const int g  = lid >> 2;
    const int t4 = lid & 3;
    const int idx0 = (g & 3) * 4 + (t4 & 1) * 2;   // a*4+d for this lane's v0 (mf/ng-invariant)
    const float gm0 = __ldg(gamma + idx0),  gm1 = __ldg(gamma + idx0 + 1);
    const float bt0 = __ldg(beta  + idx0),  bt1 = __ldg(beta  + idx0 + 1);
    const bool last_tile = (w0 == 2016);           // only tile where hi rows can overflow

#pragma unroll
    for (int mf = 0; mf < 2; ++mf) {
        const int wl_lo = 8 * wm + 4 * mf + (g >> 2);
        const int w_lo  = w0 + wl_lo;              // always < WOUTN
        const int w_hi  = w_lo + 2;
#pragma unroll
        for (int ng = 0; ng < 8; ++ng) {
            const float v0 = d[mf][ng][0], v1 = d[mf][ng][1];
            const float v2 = d[mf][ng][2], v3 = d[mf][ng][3];
            float s_lo = v0 + v1,              s_hi = v2 + v3;
            float q_lo = fmaf(v0, v0, v1 * v1), q_hi = fmaf(v2, v2, v3 * v3);
#pragma unroll
            for (int msk = 0; msk < 3; ++msk) {
                const int mask = (msk == 0) ? 1 : ((msk == 1) ? 4 : 8);
                s_lo += __shfl_xor_sync(0xffffffffu, s_lo, mask);
                q_lo += __shfl_xor_sync(0xffffffffu, q_lo, mask);
                s_hi += __shfl_xor_sync(0xffffffffu, s_hi, mask);
                q_hi += __shfl_xor_sync(0xffffffffu, q_hi, mask);
            }
            const float mu_lo  = s_lo * 0.0625f;
            const float var_lo = fmaf(q_lo, 0.0625f, -mu_lo * mu_lo);
            const float inv_lo = rsqrtf(var_lo + EPS_FOLDED);
            const float mu_hi  = s_hi * 0.0625f;
            const float var_hi = fmaf(q_hi, 0.0625f, -mu_hi * mu_hi);
            const float inv_hi = rsqrtf(var_hi + EPS_FOLDED);

            const int m = wn * 16 + 2 * ng + (t4 >> 1);
            const size_t base = (((size_t)b * MMO + m) * WOUTN + w_lo) * 16 + idx0;

            float2 o_lo, o_hi;
            o_lo.x = fmaf((v0 - mu_lo) * inv_lo, gm0, bt0);
            o_lo.y = fmaf((v1 - mu_lo) * inv_lo, gm1, bt1);
            o_hi.x = fmaf((v2 - mu_hi) * inv_hi, gm0, bt0);
            o_hi.y = fmaf((v3 - mu_hi) * inv_hi, gm1, bt1);

            *reinterpret_cast<float2*>(out + base) = o_lo;
            if (!last_tile || w_hi < WOUTN)
                *reinterpret_cast<float2*>(out + base + 32) = o_hi;   // +2 w-rows = +32 floats
        }
    }
}

extern "C" void kernel_launch(void* const* d_in, const int* in_sizes, int n_in,
                              void* d_out, int out_size) {
    const float* x     = (const float*)d_in[0];
    const float* w     = (const float*)d_in[1];
    const float* gamma = (const float*)d_in[2];
    const float* beta  = (const float*)d_in[3];
    float* out = (float*)d_out;

    prep_b<<<192, 256>>>(w);

    cudaFuncSetAttribute(caps_mma_kernel,
                         cudaFuncAttributeMaxDynamicSharedMemorySize, SMEM_BYTES);
    dim3 grid(64, BB);   // 64 w-tiles x 16 batches
    caps_mma_kernel<<<grid, THREADS, SMEM_BYTES>>>(x, gamma, beta, out);
}

// round 17
// speedup vs baseline: 1.4945x; 1.0096x over previous
#include <cuda_runtime.h>
#include <cuda_fp16.h>
#include <cstdint>

// CapsuleConv = GEMM (rows=(b,w,a)=130944, K=(k,n,x)=384, cols=(m,d)=128) + fused LayerNorm.
// Single-pass fp16 mma.sync (R16 structure: shfl-only epilogue, reg-double-buffered B) +
//  - A-build with register-staged LDG batches (all global loads in flight early)
//  - coalesced smem-transpose prep_b

#define BB    16
#define NIN   32
#define LLEN  2048
#define MMO   32
#define WOUTN 2046

#define THREADS 256
#define WTILE   32          // w per CTA (M = 128 output rows)
#define ASTRIDE 272         // smem row stride bytes (128 fp16 = 256B + 16 pad)
#define A_ROWS  136         // (WTILE + 2) * 4
#define A_MAT   (A_ROWS * ASTRIDE)        // 36992
#define B_MAT   (128 * ASTRIDE)           // 34816
#define OFF_B   A_MAT
#define SMEM_BYTES (A_MAT + 2 * B_MAT)    // 106624 -> 2 CTAs/SM
#define EPS_FOLDED 1.024e-2f              // 1e-5 * 32^2 (LN on 32x-scaled values)

// ---- persistent scratch: rearranged fp16 weight ----
__device__ __half g_B[3 * 128 * 128];     // g_B[(k*128 + c)*128 + col], c=m*4+d, col=n*4+x

// ======================= helpers =======================
__device__ __forceinline__ uint32_t smem_u32(const void* p) {
    uint32_t a;
    asm("{ .reg .u64 t; cvta.to.shared.u64 t, %1; cvt.u32.u64 %0, t; }" : "=r"(a) : "l"(p));
    return a;
}
__device__ __forceinline__ void cp16(uint32_t dst, const void* src) {
    asm volatile("cp.async.cg.shared.global [%0], [%1], 16;" :: "r"(dst), "l"(src));
}
__device__ __forceinline__ void cp_commit() {
    asm volatile("cp.async.commit_group;" ::: "memory");
}
__device__ __forceinline__ void ldsm4(uint32_t* r, uint32_t addr) {
    asm volatile("ldmatrix.sync.aligned.m8n8.x4.shared.b16 {%0,%1,%2,%3}, [%4];"
                 : "=r"(r[0]), "=r"(r[1]), "=r"(r[2]), "=r"(r[3]) : "r"(addr));
}
__device__ __forceinline__ void mma16816(float* d, const uint32_t* a,
                                         uint32_t b0, uint32_t b1) {
    asm volatile(
        "mma.sync.aligned.m16n8k16.row.col.f32.f16.f16.f32 "
        "{%0,%1,%2,%3}, {%4,%5,%6,%7}, {%8,%9}, {%0,%1,%2,%3};"
        : "+f"(d[0]), "+f"(d[1]), "+f"(d[2]), "+f"(d[3])
        : "r"(a[0]), "r"(a[1]), "r"(a[2]), "r"(a[3]), "r"(b0), "r"(b1));
}
__device__ __forceinline__ uint32_t pkh(__half a, __half b) {
    __half2 t(a, b);
    return *reinterpret_cast<uint32_t*>(&t);
}

// ======================= prepass: coalesced rearrange + convert weight =======================
// 48 blocks: k = blk>>4, n0 = (blk&15)*2. Loads contiguous 1024-float w chunk
// (k, n0..n0+1, all x/d/m) coalesced, transposes through smem, writes paired-fp16
// uint32 runs (16B contiguous per c-row).
__global__ __launch_bounds__(256)
void prep_b(const float* __restrict__ w) {
    __shared__ float st[1024];
    const int k   = blockIdx.x >> 4;
    const int n0  = (blockIdx.x & 15) * 2;
    const int tid = threadIdx.x;

    *reinterpret_cast<float4*>(st + tid * 4) = *reinterpret_cast<const float4*>(
        w + (size_t)(k * 32 + n0) * 512 + tid * 4);
    __syncthreads();

#pragma unroll
    for (int j = 0; j < 2; ++j) {
        const int u  = tid + 256 * j;     // 0..511: (c, col-pair)
        const int c  = u >> 2;            // m*4+d
        const int q0 = (u & 3) * 2;       // col offset within this block's 8 cols
        const int m = c >> 2, d = c & 3;
        // st offset of element (q = nl*4+x, d, m) = (q*4 + d)*32 + m
        const float e0 = st[(q0 * 4 + d) * 32 + m];
        const float e1 = st[((q0 + 1) * 4 + d) * 32 + m];
        *reinterpret_cast<uint32_t*>(g_B + (size_t)(k * 128 + c) * 128 + n0 * 4 + q0) =
            pkh(__float2half_rn(e0), __float2half_rn(e1));
    }
}

// ======================= main kernel =======================
__global__ __launch_bounds__(THREADS, 2)
void caps_mma_kernel(const float* __restrict__ x,
                     const float* __restrict__ gamma,
                     const float* __restrict__ beta,
                     float* __restrict__ out) {
    extern __shared__ char dsm[];
    const uint32_t smem = smem_u32(dsm);

    const int tid = threadIdx.x;
    const int wid = tid >> 5, lid = tid & 31;
    const int b  = blockIdx.y;
    const int w0 = blockIdx.x * WTILE;

    const int wm = wid & 3;           // rows wm*32 .. +32
    const int wn = wid >> 2;          // cols wn*64 .. +64
    const uint32_t lane_off = (uint32_t)((lid & 15) * ASTRIDE + (lid >> 4) * 16);

    const float* xb = x + (size_t)b * NIN * LLEN * 16;

    // ---- issue B[0] into buf0 (2048 cp16, 8/thread) ----
#pragma unroll
    for (int j = 0; j < 8; ++j) {
        const int u = tid + THREADS * j;
        const int row = u >> 4, seg = u & 15;
        cp16(smem + OFF_B + (uint32_t)(row * ASTRIDE + seg * 16),
             g_B + (size_t)row * 128 + seg * 8);
    }
    cp_commit();   // group 0: B0

    // ---- A batch 1: 4 LDG pairs into registers (in flight early) ----
    float4 sA0[4], sA1[4];
#pragma unroll
    for (int j = 0; j < 4; ++j) {
        const int P  = tid + THREADS * j;
        const int a  = P & 3;
        const int ll = (P >> 2) & 31;
        const int s  = P >> 7;
        const float* base = xb + ((size_t)(2 * s) * LLEN + (w0 + ll)) * 16 + a * 4;
        sA0[j] = *reinterpret_cast<const float4*>(base);
        sA1[j] = *reinterpret_cast<const float4*>(base + (size_t)LLEN * 16);
    }

    // ---- issue B[1] into buf1 ----
#pragma unroll
    for (int j = 0; j < 8; ++j) {
        const int u = tid + THREADS * j;
        const int row = u >> 4, seg = u & 15;
        cp16(smem + OFF_B + B_MAT + (uint32_t)(row * ASTRIDE + seg * 16),
             g_B + (size_t)(128 + row) * 128 + seg * 8);
    }
    cp_commit();   // group 1: B1

    // ---- A batch 2 + overhang LDGs ----
    float4 sB0[4], sB1[4];
#pragma unroll
    for (int j = 4; j < 8; ++j) {
        const int P  = tid + THREADS * j;
        const int a  = P & 3;
        const int ll = (P >> 2) & 31;
        const int s  = P >> 7;
        const float* base = xb + ((size_t)(2 * s) * LLEN + (w0 + ll)) * 16 + a * 4;
        sB0[j - 4] = *reinterpret_cast<const float4*>(base);
        sB1[j - 4] = *reinterpret_cast<const float4*>(base + (size_t)LLEN * 16);
    }
    float4 sO0, sO1;
    const bool has_ov = tid < 128;
    if (has_ov) {
        const int a  = tid & 3;
        const int ll = 32 + ((tid >> 2) & 1);
        const int s  = tid >> 3;
        int l = w0 + ll; if (l > LLEN - 1) l = LLEN - 1;   // garbage only for w>=WOUT
        const float* base = xb + ((size_t)(2 * s) * LLEN + l) * 16 + a * 4;
        sO0 = *reinterpret_cast<const float4*>(base);
        sO1 = *reinterpret_cast<const float4*>(base + (size_t)LLEN * 16);
    }

    // ---- convert + STS.128 all staged pairs ----
#pragma unroll
    for (int j = 0; j < 8; ++j) {
        const int P  = tid + THREADS * j;
        const int a  = P & 3;
        const int ll = (P >> 2) & 31;
        const int s  = P >> 7;
        const float4 v0 = (j < 4) ? sA0[j] : sB0[j - 4];
        const float4 v1 = (j < 4) ? sA1[j] : sB1[j - 4];
        *reinterpret_cast<uint4*>(dsm + (uint32_t)((ll * 4 + a) * ASTRIDE + s * 16)) =
            make_uint4(pkh(__float2half_rn(v0.x), __float2half_rn(v0.y)),
                       pkh(__float2half_rn(v0.z), __float2half_rn(v0.w)),
                       pkh(__float2half_rn(v1.x), __float2half_rn(v1.y)),
                       pkh(__float2half_rn(v1.z), __float2half_rn(v1.w)));
    }
    if (has_ov) {
        const int a  = tid & 3;
        const int ll = 32 + ((tid >> 2) & 1);
        const int s  = tid >> 3;
        *reinterpret_cast<uint4*>(dsm + (uint32_t)((ll * 4 + a) * ASTRIDE + s * 16)) =
            make_uint4(pkh(__float2half_rn(sO0.x), __float2half_rn(sO0.y)),
                       pkh(__float2half_rn(sO0.z), __float2half_rn(sO0.w)),
                       pkh(__float2half_rn(sO1.x), __float2half_rn(sO1.y)),
                       pkh(__float2half_rn(sO1.z), __float2half_rn(sO1.w)));
    }

    float d[2][8][4];
#pragma unroll
    for (int i = 0; i < 2; i++)
#pragma unroll
        for (int j = 0; j < 8; j++)
#pragma unroll
            for (int q = 0; q < 4; q++) d[i][j][q] = 0.0f;

    for (int k = 0; k < 3; ++k) {
        if (k == 0) {
            asm volatile("cp.async.wait_group 1;" ::: "memory");   // own B0 done
            __syncthreads();               // A STS + everyone's B0 visible
        } else if (k == 1) {
            asm volatile("cp.async.wait_group 0;" ::: "memory");   // own B1 done
            __syncthreads();               // all B1 visible AND all buf0 reads done
            // buf0 free: issue B2 into it (overlaps k1 compute)
#pragma unroll
            for (int j = 0; j < 8; ++j) {
                const int u = tid + THREADS * j;
                const int row = u >> 4, seg = u & 15;
                cp16(smem + OFF_B + (uint32_t)(row * ASTRIDE + seg * 16),
                     g_B + (size_t)(256 + row) * 128 + seg * 8);
            }
            cp_commit();   // group 2: B2
        } else {
            asm volatile("cp.async.wait_group 0;" ::: "memory");   // own B2 done
            __syncthreads();               // all B2 visible
        }

        uint32_t aA0 = smem + (uint32_t)((wm * 32 + 4 * k) * ASTRIDE) + lane_off;
        uint32_t aA1 = aA0 + 16 * ASTRIDE;
        uint32_t aB0 = smem + OFF_B + (uint32_t)((k & 1) ? B_MAT : 0)
                     + (uint32_t)(wn * 64 * ASTRIDE) + lane_off;
        uint32_t aB1 = aB0 + 16 * ASTRIDE;
        uint32_t aB2 = aB0 + 32 * ASTRIDE;
        uint32_t aB3 = aB0 + 48 * ASTRIDE;

        // register double-buffered B fragments
        uint32_t Br[2][4][4];
        ldsm4(Br[0][0], aB0); ldsm4(Br[0][1], aB1);
        ldsm4(Br[0][2], aB2); ldsm4(Br[0][3], aB3);
        aB0 += 32; aB1 += 32; aB2 += 32; aB3 += 32;

#pragma unroll
        for (int ks = 0; ks < 8; ++ks) {
            const int cur = ks & 1, nxt = cur ^ 1;
            uint32_t Ar[2][4];
            ldsm4(Ar[0], aA0); ldsm4(Ar[1], aA1);
            aA0 += 32; aA1 += 32;
            if (ks < 7) {
                ldsm4(Br[nxt][0], aB0); ldsm4(Br[nxt][1], aB1);
                ldsm4(Br[nxt][2], aB2); ldsm4(Br[nxt][3], aB3);
                aB0 += 32; aB1 += 32; aB2 += 32; aB3 += 32;
            }
#pragma unroll
            for (int mf = 0; mf < 2; ++mf)
#pragma unroll
                for (int bg = 0; bg < 4; ++bg) {
                    mma16816(d[mf][bg * 2],     Ar[mf], Br[cur][bg][0], Br[cur][bg][2]);
                    mma16816(d[mf][bg * 2 + 1], Ar[mf], Br[cur][bg][1], Br[cur][bg][3]);
                }
        }
    }

    // ======= shfl-only epilogue: no barrier, no smem =======
    const int g  = lid >> 2;
    const int t4 = lid & 3;
    const int idx0 = (g & 3) * 4 + (t4 & 1) * 2;   // a*4+d for this lane's v0
    const float gm0 = __ldg(gamma + idx0),  gm1 = __ldg(gamma + idx0 + 1);
    const float bt0 = __ldg(beta  + idx0),  bt1 = __ldg(beta  + idx0 + 1);
    const bool last_tile = (w0 == 2016);

#pragma unroll
    for (int mf = 0; mf < 2; ++mf) {
        const int wl_lo = 8 * wm + 4 * mf + (g >> 2);
        const int w_lo  = w0 + wl_lo;              // always < WOUTN
        const int w_hi  = w_lo + 2;
#pragma unroll
        for (int ng = 0; ng < 8; ++ng) {
            const float v0 = d[mf][ng][0], v1 = d[mf][ng][1];
            const float v2 = d[mf][ng][2], v3 = d[mf][ng][3];
            float s_lo = v0 + v1,              s_hi = v2 + v3;
            float q_lo = fmaf(v0, v0, v1 * v1), q_hi = fmaf(v2, v2, v3 * v3);
#pragma unroll
            for (int msk = 0; msk < 3; ++msk) {
                const int mask = (msk == 0) ? 1 : ((msk == 1) ? 4 : 8);
                s_lo += __shfl_xor_sync(0xffffffffu, s_lo, mask);
                q_lo += __shfl_xor_sync(0xffffffffu, q_lo, mask);
                s_hi += __shfl_xor_sync(0xffffffffu, s_hi, mask);
                q_hi += __shfl_xor_sync(0xffffffffu, q_hi, mask);
            }
            const float mu_lo  = s_lo * 0.0625f;
            const float var_lo = fmaf(q_lo, 0.0625f, -mu_lo * mu_lo);
            const float inv_lo = rsqrtf(var_lo + EPS_FOLDED);
            const float mu_hi  = s_hi * 0.0625f;
            const float var_hi = fmaf(q_hi, 0.0625f, -mu_hi * mu_hi);
            const float inv_hi = rsqrtf(var_hi + EPS_FOLDED);

            const int m = wn * 16 + 2 * ng + (t4 >> 1);
            const size_t base = (((size_t)b * MMO + m) * WOUTN + w_lo) * 16 + idx0;

            float2 o_lo, o_hi;
            o_lo.x = fmaf((v0 - mu_lo) * inv_lo, gm0, bt0);
            o_lo.y = fmaf((v1 - mu_lo) * inv_lo, gm1, bt1);
            o_hi.x = fmaf((v2 - mu_hi) * inv_hi, gm0, bt0);
            o_hi.y = fmaf((v3 - mu_hi) * inv_hi, gm1, bt1);

            *reinterpret_cast<float2*>(out + base) = o_lo;
            if (!last_tile || w_hi < WOUTN)
                *reinterpret_cast<float2*>(out + base + 32) = o_hi;   // +2 w-rows
        }
    }
}

extern "C" void kernel_launch(void* const* d_in, const int* in_sizes, int n_in,
                              void* d_out, int out_size) {
    const float* x     = (const float*)d_in[0];
    const float* w     = (const float*)d_in[1];
    const float* gamma = (const float*)d_in[2];
    const float* beta  = (const float*)d_in[3];
    float* out = (float*)d_out;

    prep_b<<<48, 256>>>(w);

    cudaFuncSetAttribute(caps_mma_kernel,
                         cudaFuncAttributeMaxDynamicSharedMemorySize, SMEM_BYTES);
    dim3 grid(64, BB);   // 64 w-tiles x 16 batches
    caps_mma_kernel<<<grid, THREADS, SMEM_BYTES>>>(x, gamma, beta, out);
}